// round 16
// baseline (speedup 1.0000x reference)
#include <cuda_runtime.h>

#define FULL_MASK 0xffffffffu

typedef unsigned int u32;

// Tree output: [B=16][D=256] (head h occupies channels h*32..h*32+31)
__device__ float g_tv[16 * 256];

// ---------------------------------------------------------------------------
// cp.async helpers (sm_103a: LDGSTS). .cg = bypass L1, land L2->smem.
// ---------------------------------------------------------------------------
__device__ __forceinline__ u32 smem_u32(const void* p) {
    return (u32)__cvta_generic_to_shared(p);
}
__device__ __forceinline__ void cp_async16(u32 dst, const void* src) {
    asm volatile("cp.async.cg.shared.global [%0], [%1], 16;" :: "r"(dst), "l"(src));
}
__device__ __forceinline__ void cp_commit() {
    asm volatile("cp.async.commit_group;" ::: "memory");
}
__device__ __forceinline__ void cp_wait_1() {
    asm volatile("cp.async.wait_group 1;" ::: "memory");
}

// ---------------------------------------------------------------------------
// Kernel A: LIF tree (exact R4 version — part of the 47.6us record).
// One block per (batch, head): 128 blocks x 256 threads; warp = node in level.
// ---------------------------------------------------------------------------
__device__ __forceinline__ void node_step(
    float& xk, float& xv, int node, int lane,
    float* __restrict__ Wslot,
    const float* __restrict__ W,
    const float* __restrict__ bvec, const float* __restrict__ thr,
    const float* __restrict__ tau,  const float* __restrict__ vres)
{
    const float4* __restrict__ Wn = reinterpret_cast<const float4*>(W + node * 1024);
#pragma unroll
    for (int i = lane; i < 256; i += 32) {
        const float4 wv = Wn[i];
        const int o  = i >> 3;
        const int d4 = (i & 7) << 2;
        float* dst = &Wslot[o * 33 + d4];
        dst[0] = wv.x; dst[1] = wv.y; dst[2] = wv.z; dst[3] = wv.w;
    }
    __syncwarp();

    const float* __restrict__ wrow = Wslot + lane * 33;
    float ok = 0.f, ov = 0.f;
#pragma unroll
    for (int d = 0; d < 32; ++d) {
        const float ak = __shfl_sync(FULL_MASK, xk, d);
        const float av = __shfl_sync(FULL_MASK, xv, d);
        const float w  = wrow[d];
        ok = fmaf(ak, w, ok);
        ov = fmaf(av, w, ov);
    }
    const float bl = __ldg(&bvec[node * 32 + lane]);
    ok += bl;
    ov += bl;

    const float th = __ldg(&thr[node * 32 + lane]);
    const float ta = __ldg(&tau[node * 32 + lane]);
    const float vr = __ldg(&vres[node * 32 + lane]);
    const float sk = (xk >= th) ? 1.f : 0.f;
    const float va = xk * (1.f - sk) + vr * sk;
    const float v2 = fmaf(ta, va, xv);
    const float sv = (v2 >= th) ? 1.f : 0.f;

    xk = ok * sk;
    xv = ov * sv;
}

__global__ __launch_bounds__(256) void tree_kernel(
    const float* __restrict__ key_value,
    const float* __restrict__ W,
    const float* __restrict__ bvec,
    const float* __restrict__ thr,
    const float* __restrict__ tau,
    const float* __restrict__ vres)
{
    __shared__ float Wslots[8][1056];
    __shared__ float ks[8][32];
    __shared__ float vs[8][32];

    const int tid  = threadIdx.x;
    const int lane = tid & 31;
    const int w    = tid >> 5;
    const int b    = blockIdx.x >> 3;
    const int h    = blockIdx.x & 7;

    float* Wslot = Wslots[w];

    float xk = __ldg(&key_value[(b * 16 + w) * 256 + h * 32 + lane]);
    float xv = xk;

    node_step(xk, xv, 7 + w, lane, Wslot, W, bvec, thr, tau, vres);
    ks[w][lane] = xk; vs[w][lane] = xv;
    __syncthreads();

    if (w < 4) {
        xk = 0.5f * (ks[2 * w][lane] + ks[2 * w + 1][lane]);
        xv = 0.5f * (vs[2 * w][lane] + vs[2 * w + 1][lane]);
        node_step(xk, xv, 3 + w, lane, Wslot, W, bvec, thr, tau, vres);
    }
    __syncthreads();
    if (w < 4) { ks[w][lane] = xk; vs[w][lane] = xv; }
    __syncthreads();

    if (w < 2) {
        xk = 0.5f * (ks[2 * w][lane] + ks[2 * w + 1][lane]);
        xv = 0.5f * (vs[2 * w][lane] + vs[2 * w + 1][lane]);
        node_step(xk, xv, 1 + w, lane, Wslot, W, bvec, thr, tau, vres);
    }
    __syncthreads();
    if (w < 2) { ks[w][lane] = xk; vs[w][lane] = xv; }
    __syncthreads();

    if (w == 0) {
        xk = 0.5f * (ks[0][lane] + ks[1][lane]);
        xv = 0.5f * (vs[0][lane] + vs[1][lane]);
        node_step(xk, xv, 0, lane, Wslot, W, bvec, thr, tau, vres);
        // softmax over a single tree node == 1.0 -> attn_out = tree_v broadcast
        g_tv[b * 256 + h * 32 + lane] = xv;
    }
}

// ---------------------------------------------------------------------------
// Kernel B: persistent warp-local cp.async-pipelined residual-add + LayerNorm.
// 888 blocks (one wave at 6/SM), 8 warps/block. Each warp owns a private
// 3-stage x 1KB smem buffer and streams rows r = gw + i*7104, i<19 (uniform
// trip count; out-of-range iterations issue empty commit groups). Loads for
// tile i+2 are issued async (L1-bypass) while tile i computes -> loop-carried
// MLP without register cost and ZERO block-level barriers.
// ---------------------------------------------------------------------------
__global__ __launch_bounds__(256, 6) void ln_kernel(
    const float* __restrict__ query,
    const float* __restrict__ gamma,
    const float* __restrict__ beta,
    float* __restrict__ out)
{
    __shared__ float buf[8][3][256];   // [warp][stage][floats] = 24 KB

    const int lane = threadIdx.x & 31;
    const int w    = threadIdx.x >> 5;
    const int gw   = blockIdx.x * 8 + w;     // 0..7103
    const int NW   = 7104;

    const float4* __restrict__ g4  = reinterpret_cast<const float4*>(gamma);
    const float4* __restrict__ be4 = reinterpret_cast<const float4*>(beta);
    const float4* __restrict__ tv4 = reinterpret_cast<const float4*>(g_tv);
    float4* __restrict__ o4 = reinterpret_cast<float4*>(out);

    // this lane's 32-byte slice base inside its warp's stage-0 buffer
    const u32 dst0 = smem_u32(&buf[w][0][lane * 8]);

    // issue loads for tile i (row gw + i*NW) into stage i%3; ALWAYS commit
    // (empty group when out of range) so group accounting stays uniform.
    auto issue = [&](int i) {
        const long long r = (long long)gw + (long long)i * NW;
        if (r < 131072 && i < 19) {
            const float* src = query + r * 256 + lane * 8;
            const u32 d = dst0 + (u32)((i % 3) * 1024);
            cp_async16(d,      src);
            cp_async16(d + 16, src + 4);
        }
        cp_commit();
    };

    issue(0);
    issue(1);

#pragma unroll 1
    for (int i = 0; i < 19; ++i) {
        const long long r = (long long)gw + (long long)i * NW;
        const bool valid = (r < 131072);      // warp-uniform

        cp_wait_1();          // group i complete (at most group i+1 pending)
        __syncwarp();         // publish cp.async smem writes warp-wide

        float4 x0, x1;
        if (valid) {
            const float4* row = reinterpret_cast<const float4*>(&buf[w][i % 3][0]);
            x0 = row[lane];
            x1 = row[lane + 32];
        }
        __syncwarp();         // all lanes done reading before stage reuse
        issue(i + 2);         // prefetch 2 tiles ahead into stage (i+2)%3

        if (valid) {
            const int bb = (int)(r >> 13);
            const float4* __restrict__ tvr = tv4 + bb * 64;
            const float4 t0 = __ldg(&tvr[lane]);
            const float4 t1 = __ldg(&tvr[lane + 32]);

            x0.x += t0.x; x0.y += t0.y; x0.z += t0.z; x0.w += t0.w;
            x1.x += t1.x; x1.y += t1.y; x1.z += t1.z; x1.w += t1.w;

            float s  = x0.x + x0.y + x0.z + x0.w + x1.x + x1.y + x1.z + x1.w;
            float ss = x0.x*x0.x + x0.y*x0.y + x0.z*x0.z + x0.w*x0.w
                     + x1.x*x1.x + x1.y*x1.y + x1.z*x1.z + x1.w*x1.w;

#pragma unroll
            for (int off = 16; off > 0; off >>= 1) {
                s  += __shfl_xor_sync(FULL_MASK, s,  off);
                ss += __shfl_xor_sync(FULL_MASK, ss, off);
            }

            const float m   = s * (1.f / 256.f);
            const float inv = rsqrtf(ss * (1.f / 256.f) - m * m + 1e-5f);

            const float4 g0 = __ldg(&g4[lane]);
            const float4 g1 = __ldg(&g4[lane + 32]);
            const float4 b0 = __ldg(&be4[lane]);
            const float4 b1 = __ldg(&be4[lane + 32]);

            float4 y0, y1;
            y0.x = fmaf((x0.x - m) * inv, g0.x, b0.x);
            y0.y = fmaf((x0.y - m) * inv, g0.y, b0.y);
            y0.z = fmaf((x0.z - m) * inv, g0.z, b0.z);
            y0.w = fmaf((x0.w - m) * inv, g0.w, b0.w);
            y1.x = fmaf((x1.x - m) * inv, g1.x, b1.x);
            y1.y = fmaf((x1.y - m) * inv, g1.y, b1.y);
            y1.z = fmaf((x1.z - m) * inv, g1.z, b1.z);
            y1.w = fmaf((x1.w - m) * inv, g1.w, b1.w);

            float4* __restrict__ orow = o4 + r * 64;
            orow[lane]      = y0;
            orow[lane + 32] = y1;
        }
    }
}

// ---------------------------------------------------------------------------
// Inputs (metadata order): query, key_value, W, b, thr, tau, vres, gamma, beta
// Output: float32, 16*8192*256 elements
// ---------------------------------------------------------------------------
extern "C" void kernel_launch(void* const* d_in, const int* in_sizes, int n_in,
                              void* d_out, int out_size)
{
    (void)in_sizes; (void)n_in; (void)out_size;
    const float* query = (const float*)d_in[0];
    const float* kv    = (const float*)d_in[1];
    const float* W     = (const float*)d_in[2];
    const float* bvec  = (const float*)d_in[3];
    const float* thr   = (const float*)d_in[4];
    const float* tau   = (const float*)d_in[5];
    const float* vres  = (const float*)d_in[6];
    const float* gamma = (const float*)d_in[7];
    const float* beta  = (const float*)d_in[8];
    float* out = (float*)d_out;

    // Kernel A: one block per (batch, head); warp = node within level
    tree_kernel<<<128, 256>>>(kv, W, bvec, thr, tau, vres);

    // Kernel B: persistent single-wave pipelined LN (888 = 6/SM x 148 SMs)
    ln_kernel<<<888, 256>>>(query, gamma, beta, out);
}

// round 17
// speedup vs baseline: 1.2878x; 1.2878x over previous
#include <cuda_runtime.h>

#define FULL_MASK 0xffffffffu

// Scratch for tree_v, laid out as [B=16][D=256] (head h occupies channels h*32..h*32+31)
__device__ float g_tv[16 * 256];

// ---------------------------------------------------------------------------
// Kernel A: LIF tree. One block per (batch, head): 128 blocks x 256 threads.
// Warp l owns node l of the current level (level1: 8 warps run 8 nodes
// concurrently). Each warp stages ONLY its node's W into a warp-private
// padded smem slot (stride-33 rows -> conflict-free LDS; __syncwarp only).
// Merges between levels go through a small smem buffer + __syncthreads.
// ---------------------------------------------------------------------------
__device__ __forceinline__ void node_step(
    float& xk, float& xv, int node, int lane,
    float* __restrict__ Wslot,
    const float* __restrict__ W,
    const float* __restrict__ bvec, const float* __restrict__ thr,
    const float* __restrict__ tau,  const float* __restrict__ vres)
{
    // stage W[node] (32x32) into Wslot with padding: 8 float4 per lane, coalesced
    const float4* __restrict__ Wn = reinterpret_cast<const float4*>(W + node * 1024);
#pragma unroll
    for (int i = lane; i < 256; i += 32) {
        const float4 w = Wn[i];
        const int o  = i >> 3;
        const int d4 = (i & 7) << 2;
        float* dst = &Wslot[o * 33 + d4];
        dst[0] = w.x; dst[1] = w.y; dst[2] = w.z; dst[3] = w.w;
    }
    __syncwarp();

    const float* __restrict__ wrow = Wslot + lane * 33;
    float ok = 0.f, ov = 0.f;
#pragma unroll
    for (int d = 0; d < 32; ++d) {
        const float ak = __shfl_sync(FULL_MASK, xk, d);
        const float av = __shfl_sync(FULL_MASK, xv, d);
        const float w  = wrow[d];
        ok = fmaf(ak, w, ok);
        ov = fmaf(av, w, ov);
    }
    const float bl = __ldg(&bvec[node * 32 + lane]);
    ok += bl;
    ov += bl;

    const float th = __ldg(&thr[node * 32 + lane]);
    const float ta = __ldg(&tau[node * 32 + lane]);
    const float vr = __ldg(&vres[node * 32 + lane]);
    const float sk = (xk >= th) ? 1.f : 0.f;
    const float va = xk * (1.f - sk) + vr * sk;
    const float v2 = fmaf(ta, va, xv);
    const float sv = (v2 >= th) ? 1.f : 0.f;

    xk = ok * sk;
    xv = ov * sv;
}

__global__ __launch_bounds__(256) void tree_kernel(
    const float* __restrict__ key_value,
    const float* __restrict__ W,
    const float* __restrict__ bvec,
    const float* __restrict__ thr,
    const float* __restrict__ tau,
    const float* __restrict__ vres)
{
    __shared__ float Wslots[8][1056];   // warp-private staging, 33792 B
    __shared__ float ks[8][32];
    __shared__ float vs[8][32];

    const int tid  = threadIdx.x;
    const int lane = tid & 31;
    const int w    = tid >> 5;          // warp id = node index within level
    const int b    = blockIdx.x >> 3;
    const int h    = blockIdx.x & 7;

    float* Wslot = Wslots[w];

    // leaf w: key_value[b, w, h*32 + lane]
    float xk = __ldg(&key_value[(b * 16 + w) * 256 + h * 32 + lane]);
    float xv = xk;

    // ---- level 1: 8 nodes (7..14), all warps active -------------------------
    node_step(xk, xv, 7 + w, lane, Wslot, W, bvec, thr, tau, vres);
    ks[w][lane] = xk; vs[w][lane] = xv;
    __syncthreads();

    // ---- level 2: 4 nodes (3..6) --------------------------------------------
    if (w < 4) {
        xk = 0.5f * (ks[2 * w][lane] + ks[2 * w + 1][lane]);
        xv = 0.5f * (vs[2 * w][lane] + vs[2 * w + 1][lane]);
        node_step(xk, xv, 3 + w, lane, Wslot, W, bvec, thr, tau, vres);
    }
    __syncthreads();
    if (w < 4) { ks[w][lane] = xk; vs[w][lane] = xv; }
    __syncthreads();

    // ---- level 3: 2 nodes (1..2) --------------------------------------------
    if (w < 2) {
        xk = 0.5f * (ks[2 * w][lane] + ks[2 * w + 1][lane]);
        xv = 0.5f * (vs[2 * w][lane] + vs[2 * w + 1][lane]);
        node_step(xk, xv, 1 + w, lane, Wslot, W, bvec, thr, tau, vres);
    }
    __syncthreads();
    if (w < 2) { ks[w][lane] = xk; vs[w][lane] = xv; }
    __syncthreads();

    // ---- level 4: root node 0 ------------------------------------------------
    if (w == 0) {
        xk = 0.5f * (ks[0][lane] + ks[1][lane]);
        xv = 0.5f * (vs[0][lane] + vs[1][lane]);
        node_step(xk, xv, 0, lane, Wslot, W, bvec, thr, tau, vres);
        // softmax over a single tree node == 1.0 -> attn_out = tree_v broadcast
        g_tv[b * 256 + h * 32 + lane] = xv;
    }
}

// ---------------------------------------------------------------------------
// Kernel B: fused residual-add + LayerNorm. One warp per FOUR rows (D=256):
// 8 independent LDG.128 in flight per warp. 268 MB mandatory HBM traffic.
// ---------------------------------------------------------------------------
__global__ __launch_bounds__(256) void ln_kernel(
    const float* __restrict__ query,
    const float* __restrict__ gamma,
    const float* __restrict__ beta,
    float* __restrict__ out)
{
    const int  lane = threadIdx.x & 31;
    const long long warp = (long long)blockIdx.x * 8 + (threadIdx.x >> 5);
    const long long r0 = warp * 4;           // rows r0..r0+3 (same batch)
    const int  b = (int)(r0 >> 13);

    const float4* __restrict__ qr  = reinterpret_cast<const float4*>(query) + r0 * 64;
    const float4* __restrict__ tvr = reinterpret_cast<const float4*>(g_tv) + b * 64;
    const float4* __restrict__ g4  = reinterpret_cast<const float4*>(gamma);
    const float4* __restrict__ be4 = reinterpret_cast<const float4*>(beta);

    // 8 independent streaming row loads in flight
    float4 q[4][2];
#pragma unroll
    for (int r = 0; r < 4; ++r) {
        q[r][0] = __ldcs(&qr[r * 64 + lane]);
        q[r][1] = __ldcs(&qr[r * 64 + lane + 32]);
    }
    const float4 t0 = tvr[lane];
    const float4 t1 = tvr[lane + 32];

    float s[4], ss[4];
#pragma unroll
    for (int r = 0; r < 4; ++r) {
        float4 x0 = make_float4(q[r][0].x + t0.x, q[r][0].y + t0.y,
                                q[r][0].z + t0.z, q[r][0].w + t0.w);
        float4 x1 = make_float4(q[r][1].x + t1.x, q[r][1].y + t1.y,
                                q[r][1].z + t1.z, q[r][1].w + t1.w);
        q[r][0] = x0; q[r][1] = x1;
        s[r]  = x0.x + x0.y + x0.z + x0.w + x1.x + x1.y + x1.z + x1.w;
        ss[r] = x0.x*x0.x + x0.y*x0.y + x0.z*x0.z + x0.w*x0.w
              + x1.x*x1.x + x1.y*x1.y + x1.z*x1.z + x1.w*x1.w;
    }

#pragma unroll
    for (int off = 16; off > 0; off >>= 1) {
#pragma unroll
        for (int r = 0; r < 4; ++r) {
            s[r]  += __shfl_xor_sync(FULL_MASK, s[r],  off);
            ss[r] += __shfl_xor_sync(FULL_MASK, ss[r], off);
        }
    }

    const float4 g0 = __ldg(&g4[lane]);
    const float4 g1 = __ldg(&g4[lane + 32]);
    const float4 b0 = __ldg(&be4[lane]);
    const float4 b1 = __ldg(&be4[lane + 32]);

    float4* __restrict__ o4 = reinterpret_cast<float4*>(out) + r0 * 64;
#pragma unroll
    for (int r = 0; r < 4; ++r) {
        const float m   = s[r] * (1.f / 256.f);
        const float inv = rsqrtf(ss[r] * (1.f / 256.f) - m * m + 1e-5f);
        float4 y0, y1;
        y0.x = fmaf((q[r][0].x - m) * inv, g0.x, b0.x);
        y0.y = fmaf((q[r][0].y - m) * inv, g0.y, b0.y);
        y0.z = fmaf((q[r][0].z - m) * inv, g0.z, b0.z);
        y0.w = fmaf((q[r][0].w - m) * inv, g0.w, b0.w);
        y1.x = fmaf((q[r][1].x - m) * inv, g1.x, b1.x);
        y1.y = fmaf((q[r][1].y - m) * inv, g1.y, b1.y);
        y1.z = fmaf((q[r][1].z - m) * inv, g1.z, b1.z);
        y1.w = fmaf((q[r][1].w - m) * inv, g1.w, b1.w);
        __stcs(&o4[r * 64 + lane],      y0);
        __stcs(&o4[r * 64 + lane + 32], y1);
    }
}

// ---------------------------------------------------------------------------
// Inputs (metadata order): query, key_value, W, b, thr, tau, vres, gamma, beta
// Output: float32, 16*8192*256 elements
// ---------------------------------------------------------------------------
extern "C" void kernel_launch(void* const* d_in, const int* in_sizes, int n_in,
                              void* d_out, int out_size)
{
    (void)in_sizes; (void)n_in; (void)out_size;
    const float* query = (const float*)d_in[0];
    const float* kv    = (const float*)d_in[1];
    const float* W     = (const float*)d_in[2];
    const float* bvec  = (const float*)d_in[3];
    const float* thr   = (const float*)d_in[4];
    const float* tau   = (const float*)d_in[5];
    const float* vres  = (const float*)d_in[6];
    const float* gamma = (const float*)d_in[7];
    const float* beta  = (const float*)d_in[8];
    float* out = (float*)d_out;

    // Kernel A: one block per (batch, head); warp = node within level
    tree_kernel<<<128, 256>>>(kv, W, bvec, thr, tau, vres);

    // Kernel B: 131072 rows, 4 rows/warp, 8 warps/block -> 4096 blocks
    ln_kernel<<<4096, 256>>>(query, gamma, beta, out);
}